// round 12
// baseline (speedup 1.0000x reference)
#include <cuda_runtime.h>
#include <cuda_bf16.h>
#include <math.h>
#include <stdint.h>

// Problem constants
#define BB   2
#define LL   2048
#define HID  2048
#define HH   16
#define DD   128
#define MM   (BB*LL)          // 4096
#define CHK  64               // scan chunk length
#define NCH  (LL/CHK)         // 32 chunks
#define DV   32               // v-dim split per state block
#define NSPLIT 4              // 128 / DV
#define NBH  (BB*HH)          // 32

// ---------------- device scratch (no cudaMalloc allowed) ----------------
__device__ __align__(256) float g_q   [MM*HID];     // phi_q [b*H+h][t][d]
__device__ __align__(256) float g_k   [MM*HID];     // phi_k
__device__ __align__(256) float g_v   [MM*HID];     // v
__device__ __align__(256) float g_beta[NBH*LL];     // [b*H+h][t]

// chunk-factored scan scratch
__device__ __align__(256) float g_At  [NBH*NCH*CHK*CHK];  // decayed+masked A, [bhch][s][i]
__device__ __align__(256) float g_rsum[NBH*NCH*CHK];
__device__ __align__(256) float g_eLc [NBH*NCH*CHK];
__device__ __align__(256) float g_ksc [NBH*NCH*CHK];
__device__ __align__(256) float g_Sst [NBH*NCH*DD*DD];    // S_prev per chunk
__device__ __align__(256) float g_zst [NBH*NCH*DD];       // z_prev per chunk

// bf16 split buffers
__device__ __align__(256) __nv_bfloat16 g_ahi[MM*HID];       // x (then y) hi
__device__ __align__(256) __nv_bfloat16 g_alo[MM*HID];       // x (then y) lo
__device__ __align__(256) __nv_bfloat16 g_whi[4*HID*HID];    // W^T hi (q,k,v,o concat)
__device__ __align__(256) __nv_bfloat16 g_wlo[4*HID*HID];    // W^T lo

// rope tables
__device__ float g_cos[LL*64];
__device__ float g_sin[LL*64];

// =====================================================================
// sm_80-era primitives (legal on plain sm_103 ptxas target)
// =====================================================================
__device__ __forceinline__ uint32_t smem_u32(const void* p) {
    uint32_t a;
    asm("{ .reg .u64 t; cvta.to.shared.u64 t, %1; cvt.u32.u64 %0, t; }"
        : "=r"(a) : "l"(p));
    return a;
}
__device__ __forceinline__ void ldsm_x4(uint32_t addr, uint32_t& r0, uint32_t& r1,
                                        uint32_t& r2, uint32_t& r3) {
    asm volatile("ldmatrix.sync.aligned.m8n8.x4.shared.b16 {%0,%1,%2,%3}, [%4];"
        : "=r"(r0), "=r"(r1), "=r"(r2), "=r"(r3) : "r"(addr));
}
__device__ __forceinline__ void mma_bf16(float* c, const uint32_t* a, const uint32_t* b) {
    asm volatile(
        "mma.sync.aligned.m16n8k16.row.col.f32.bf16.bf16.f32 "
        "{%0,%1,%2,%3}, {%4,%5,%6,%7}, {%8,%9}, {%0,%1,%2,%3};"
        : "+f"(c[0]), "+f"(c[1]), "+f"(c[2]), "+f"(c[3])
        : "r"(a[0]), "r"(a[1]), "r"(a[2]), "r"(a[3]), "r"(b[0]), "r"(b[1]));
}
#define CP_ASYNC16(dst, src) \
    asm volatile("cp.async.cg.shared.global [%0], [%1], 16;" :: "r"(dst), "l"(src))
#define CP_COMMIT() asm volatile("cp.async.commit_group;" ::: "memory")
#define CP_WAIT(n)  asm volatile("cp.async.wait_group %0;" :: "n"(n) : "memory")

// =====================================================================
// bf16 split conversion: hi = bf16(x), lo = bf16(x - hi)
// =====================================================================
__global__ __launch_bounds__(256) void cvt_split_kernel(
    const float4* __restrict__ in, __nv_bfloat16* __restrict__ hi,
    __nv_bfloat16* __restrict__ lo, int n4)
{
    int i = blockIdx.x * 256 + threadIdx.x;
    if (i >= n4) return;
    float4 v = in[i];
    float a[4] = {v.x, v.y, v.z, v.w};
    __nv_bfloat16 hb[4], lb[4];
    #pragma unroll
    for (int j = 0; j < 4; j++) {
        hb[j] = __float2bfloat16(a[j]);
        lb[j] = __float2bfloat16(a[j] - __bfloat162float(hb[j]));
    }
    __nv_bfloat162 h0, h1, l0, l1;
    h0.x = hb[0]; h0.y = hb[1]; h1.x = hb[2]; h1.y = hb[3];
    l0.x = lb[0]; l0.y = lb[1]; l1.x = lb[2]; l1.y = lb[3];
    *(__nv_bfloat162*)(hi + 4*(size_t)i)     = h0;
    *(__nv_bfloat162*)(hi + 4*(size_t)i + 2) = h1;
    *(__nv_bfloat162*)(lo + 4*(size_t)i)     = l0;
    *(__nv_bfloat162*)(lo + 4*(size_t)i + 2) = l1;
}

// All 4 weights in one launch: W [K=HID][N=HID] fp32 -> W^T hi/lo bf16 [N][K]
// blockIdx.z selects the weight.
__global__ __launch_bounds__(256) void cvt_w_kernel(
    const float* __restrict__ W0, const float* __restrict__ W1,
    const float* __restrict__ W2, const float* __restrict__ W3,
    __nv_bfloat16* __restrict__ th, __nv_bfloat16* __restrict__ tl)
{
    __shared__ float t[32][33];
    const float* W = (blockIdx.z == 0) ? W0 : (blockIdx.z == 1) ? W1
                   : (blockIdx.z == 2) ? W2 : W3;
    const size_t obase = (size_t)blockIdx.z * HID * HID;
    const int k0 = blockIdx.y * 32, n0 = blockIdx.x * 32;
    const int tx = threadIdx.x, ty = threadIdx.y;   // block (32,8)
    for (int i = ty; i < 32; i += 8)
        t[i][tx] = W[(size_t)(k0 + i) * HID + n0 + tx];
    __syncthreads();
    for (int i = ty; i < 32; i += 8) {
        float x = t[tx][i];                    // W[k0+tx][n0+i]
        __nv_bfloat16 h = __float2bfloat16(x);
        __nv_bfloat16 l = __float2bfloat16(x - __bfloat162float(h));
        size_t o = obase + (size_t)(n0 + i) * HID + k0 + tx;
        th[o] = h; tl[o] = l;
    }
}

// =====================================================================
// mma.sync GEMM with fused epilogue + register-double-buffered frags.
// C[M,N] = A[M,K] @ W[K,N] (+bias), bf16 hi/lo split (3 passes).
// 128x128 CTA tile, 8 warps (2x4), 64x32 warp tile, K-stage 64,
// 3-stage cp.async pipeline, frag prefetch hides ldmatrix latency.
// =====================================================================
#define GEMM_SMEM (3 * 4 * 16384)   // 3 stages x (Ah,Al,Bh,Bl) x 16KB = 192KB

__global__ __launch_bounds__(256, 1) void gemm_tc_kernel(
    const __nv_bfloat16* __restrict__ Ah, const __nv_bfloat16* __restrict__ Al,
    const __nv_bfloat16* __restrict__ Bh, const __nv_bfloat16* __restrict__ Bl,
    const float* __restrict__ bias, float* __restrict__ C,
    float* __restrict__ outQ, float* __restrict__ outK, float* __restrict__ outV,
    int fuse, int M, int N, int K)
{
    extern __shared__ __align__(1024) char smem[];
    const uint32_t sbase = smem_u32(smem);

    const int tid  = threadIdx.x;
    const int wid  = tid >> 5, lane = tid & 31;
    const int wm   = wid >> 2, wn = wid & 3;       // warp grid 2x4
    const int m0   = blockIdx.y * 128;
    const int bn0  = blockIdx.x * 128;             // row into B (concat N)

    const __nv_bfloat16* gsrc[4] = {Ah, Al, Bh, Bl};
    const int NS = K >> 6;                          // K/64 stages

    auto load_stage = [&](int buf, int k0e) {
        const uint32_t bs = sbase + buf * 65536;
        #pragma unroll
        for (int p = 0; p < 16; p++) {
            int idx = tid + p * 256;
            int j   = idx >> 10;
            int i   = idx & 1023;
            int r   = i >> 3, ch = i & 7;
            int phys = ch ^ (r & 7);
            uint32_t dst = bs + j * 16384 + r * 128 + phys * 16;
            int grow = (j < 2 ? m0 : bn0) + r;
            const __nv_bfloat16* src = gsrc[j] + (size_t)grow * K + k0e + ch * 8;
            CP_ASYNC16(dst, src);
        }
        CP_COMMIT();
    };

    const int lw  = lane & 7;
    const int gA  = (lane >> 4) & 1;
    const int gB  = (lane >> 3) & 1;
    uint32_t offA[4], offB[2];
    #pragma unroll
    for (int mi = 0; mi < 4; mi++)
        offA[mi] = (uint32_t)(wm * 64 + mi * 16 + (lane & 15)) * 128;
    #pragma unroll
    for (int p = 0; p < 2; p++)
        offB[p] = (uint32_t)(wn * 32 + p * 16 + ((lane >> 4) & 1) * 8 + lw) * 128;

    // double-buffered fragments (buffer index is compile-time: kk&1)
    uint32_t ah[2][4][4], al[2][4][4], bh[2][4][2], bl[2][4][2];

    auto prefetch = [&](int pb, uint32_t stage, int kk) {
        const uint32_t swA = (uint32_t)(((kk * 2 + gA) ^ lw) << 4);
        const uint32_t swB = (uint32_t)(((kk * 2 + gB) ^ lw) << 4);
        #pragma unroll
        for (int mi = 0; mi < 4; mi++) {
            uint32_t aA = stage + offA[mi] + swA;
            ldsm_x4(aA,         ah[pb][mi][0], ah[pb][mi][1], ah[pb][mi][2], ah[pb][mi][3]);
            ldsm_x4(aA + 16384, al[pb][mi][0], al[pb][mi][1], al[pb][mi][2], al[pb][mi][3]);
        }
        #pragma unroll
        for (int p = 0; p < 2; p++) {
            uint32_t aB = stage + 32768 + offB[p] + swB;
            uint32_t r0, r1, r2, r3;
            ldsm_x4(aB, r0, r1, r2, r3);
            bh[pb][2*p][0] = r0; bh[pb][2*p][1] = r1;
            bh[pb][2*p+1][0] = r2; bh[pb][2*p+1][1] = r3;
            ldsm_x4(aB + 16384, r0, r1, r2, r3);
            bl[pb][2*p][0] = r0; bl[pb][2*p][1] = r1;
            bl[pb][2*p+1][0] = r2; bl[pb][2*p+1][1] = r3;
        }
    };

    float acc[4][4][4];
    #pragma unroll
    for (int mi = 0; mi < 4; mi++)
        #pragma unroll
        for (int ni = 0; ni < 4; ni++) {
            acc[mi][ni][0] = 0.f; acc[mi][ni][1] = 0.f;
            acc[mi][ni][2] = 0.f; acc[mi][ni][3] = 0.f;
        }

    load_stage(0, 0);
    load_stage(1, 64);
    CP_WAIT(1);
    __syncthreads();
    prefetch(0, sbase, 0);

    for (int s = 0; s < NS; s++) {
        const uint32_t stage = sbase + (s % 3) * 65536;
        #pragma unroll
        for (int kk = 0; kk < 4; kk++) {
            const int cur = kk & 1;
            if (kk < 3) prefetch(cur ^ 1, stage, kk + 1);
            else if (s + 1 < NS) {
                if (s + 2 < NS) load_stage((s + 2) % 3, (s + 2) * 64);
                CP_WAIT(1);
                __syncthreads();
                prefetch(cur ^ 1, sbase + ((s + 1) % 3) * 65536, 0);
            }
            #pragma unroll
            for (int mi = 0; mi < 4; mi++)
                #pragma unroll
                for (int ni = 0; ni < 4; ni++) {
                    mma_bf16(acc[mi][ni], ah[cur][mi], bh[cur][ni]);
                    mma_bf16(acc[mi][ni], ah[cur][mi], bl[cur][ni]);
                    mma_bf16(acc[mi][ni], al[cur][mi], bh[cur][ni]);
                }
        }
    }

    const int qr = lane >> 2, qc = (lane & 3) * 2;

    if (!fuse) {
        #pragma unroll
        for (int mi = 0; mi < 4; mi++) {
            const int row = m0 + wm * 64 + mi * 16 + qr;
            #pragma unroll
            for (int ni = 0; ni < 4; ni++) {
                const int col = bn0 + wn * 32 + ni * 8 + qc;
                float b0 = bias ? bias[col]     : 0.f;
                float b1 = bias ? bias[col + 1] : 0.f;
                float2 v0 = make_float2(acc[mi][ni][0] + b0, acc[mi][ni][1] + b1);
                float2 v1 = make_float2(acc[mi][ni][2] + b0, acc[mi][ni][3] + b1);
                *(float2*)(C + (size_t)row * N + col)       = v0;
                *(float2*)(C + (size_t)(row + 8) * N + col) = v1;
            }
        }
        return;
    }

    // fused QKV epilogue
    __syncthreads();
    float* st = (float*)smem;                      // [128][132]
    #pragma unroll
    for (int mi = 0; mi < 4; mi++) {
        const int r0r = wm * 64 + mi * 16 + qr;
        #pragma unroll
        for (int ni = 0; ni < 4; ni++) {
            const int c = wn * 32 + ni * 8 + qc;
            *(float2*)&st[(size_t)r0r * 132 + c] =
                make_float2(acc[mi][ni][0], acc[mi][ni][1]);
            *(float2*)&st[(size_t)(r0r + 8) * 132 + c] =
                make_float2(acc[mi][ni][2], acc[mi][ni][3]);
        }
    }
    __syncthreads();

    const int hIdx = blockIdx.x & 15;
    if (blockIdx.x < 32) {
        float* dstBase = (blockIdx.x < 16) ? outQ : outK;
        const int j = tid & 63;
        #pragma unroll 4
        for (int it = 0; it < 32; it++) {
            const int r = (tid >> 6) + it * 4;
            const int tg = m0 + r;
            const int bI = tg >> 11, t = tg & (LL - 1);
            float xe = st[(size_t)r * 132 + j];
            float xo = st[(size_t)r * 132 + 64 + j];
            float c = g_cos[t * 64 + j];
            float s = g_sin[t * 64 + j];
            float oe = xe * c - xo * s;
            float oo = xe * s + xo * c;
            oe = (oe > 0.f) ? (oe + 1.f) : expf(oe);
            oo = (oo > 0.f) ? (oo + 1.f) : expf(oo);
            float* dst = dstBase + ((size_t)(bI * HH + hIdx) * LL + t) * DD;
            dst[j]      = oe;
            dst[j + 64] = oo;
        }
    } else {
        const int d = tid & 127;
        #pragma unroll 4
        for (int it = 0; it < 64; it++) {
            const int r = (tid >> 7) + it * 2;
            const int tg = m0 + r;
            const int bI = tg >> 11, t = tg & (LL - 1);
            outV[((size_t)(bI * HH + hIdx) * LL + t) * DD + d] =
                st[(size_t)r * 132 + d];
        }
    }
}

// =====================================================================
// rope table
// =====================================================================
__global__ __launch_bounds__(256) void rope_table_kernel()
{
    int idx = blockIdx.x * 256 + threadIdx.x;
    if (idx >= LL * 64) return;
    int t = idx >> 6, j = idx & 63;
    float invf = (float)exp(-(double)j * 9.210340371976184 / 64.0);
    float ang = (float)t * invf;
    double sd, cd; sincos((double)ang, &sd, &cd);
    g_cos[idx] = (float)cd;
    g_sin[idx] = (float)sd;
}

// =====================================================================
// beta = clip(sigmoid(x @ Wg + bg), 0.8, 0.9995), stored [b*H+h][t]
// =====================================================================
__global__ __launch_bounds__(512) void beta_kernel(
    const float* __restrict__ x, const float* __restrict__ Wg,
    const float* __restrict__ bg, float* __restrict__ beta)
{
    __shared__ float row[HID];
    const int m = blockIdx.x;
    for (int i = threadIdx.x; i < HID; i += 512) row[i] = x[(size_t)m * HID + i];
    __syncthreads();
    const int w = threadIdx.x >> 5, lane = threadIdx.x & 31;
    float s = 0.f;
    for (int d = lane; d < HID; d += 32) s = fmaf(row[d], Wg[d * HH + w], s);
    #pragma unroll
    for (int o = 16; o; o >>= 1) s += __shfl_xor_sync(0xffffffffu, s, o);
    if (lane == 0) {
        s += bg[w];
        float bt = 1.f / (1.f + expf(-s));
        bt = fminf(fmaxf(bt, 0.8f), 0.9995f);
        const int b = m >> 11, t = m & (LL - 1);
        beta[(size_t)(b * HH + w) * LL + t] = bt;
    }
}

// =====================================================================
// chunk_kernel: per (bh, chunk), fully parallel.
// =====================================================================
#define CHUNK_SMEM ((128*68*2 + 64*68 + 2*64) * 4)

__global__ __launch_bounds__(256) void chunk_kernel(
    const float* __restrict__ gq, const float* __restrict__ gk,
    const float* __restrict__ gbeta)
{
    extern __shared__ float sm[];
    float* Qt = sm;                  // [128][68]
    float* Kt = Qt + 128*68;
    float* At = Kt + 128*68;         // [64][68] s-major
    float* bl = At + 64*68;          // [64]
    float* Lc = bl + 64;             // [64]

    const int tid  = threadIdx.x;
    const int bhch = blockIdx.x;
    const int bh   = bhch >> 5, ch = bhch & 31;
    const int t0   = ch * CHK;

    const float* qp = gq + (size_t)bh*LL*DD;
    const float* kp = gk + (size_t)bh*LL*DD;
    const float* bp = gbeta + (size_t)bh*LL;

    for (int idx = tid; idx < CHK*128; idx += 256) {
        const int i = idx >> 7, d = idx & 127;
        Qt[d*68 + i] = qp[(size_t)(t0+i)*DD + d];
        Kt[d*68 + i] = kp[(size_t)(t0+i)*DD + d];
    }
    if (tid < CHK) bl[tid] = logf(bp[t0+tid]);
    __syncthreads();
    if (tid == 0) {
        float a = 0.f;
        for (int i = 0; i < CHK; i++) { a += bl[i]; Lc[i] = a; }
    }
    __syncthreads();

    const int txA = tid & 15, tyA = tid >> 4;
    float accA[4][4];
    #pragma unroll
    for (int i=0;i<4;i++) { accA[i][0]=0;accA[i][1]=0;accA[i][2]=0;accA[i][3]=0; }
    for (int k = 0; k < 128; k++) {
        float4 qa = *(float4*)&Qt[k*68 + (tyA<<2)];
        float4 kb = *(float4*)&Kt[k*68 + (txA<<2)];
        const float qv[4] = {qa.x,qa.y,qa.z,qa.w};
        const float kv[4] = {kb.x,kb.y,kb.z,kb.w};
        #pragma unroll
        for (int i=0;i<4;i++)
            #pragma unroll
            for (int s=0;s<4;s++)
                accA[i][s] = fmaf(qv[i], kv[s], accA[i][s]);
    }
    if (tid < CHK) {
        g_eLc[(size_t)bhch*CHK + tid] = expf(Lc[tid]);
        g_ksc[(size_t)bhch*CHK + tid] = expf(Lc[CHK-1] - Lc[tid]);
    }
    #pragma unroll
    for (int ss=0; ss<4; ss++) {
        const int s = (txA<<2) + ss;
        float4 av;
        float* a4 = (float*)&av;
        #pragma unroll
        for (int ii=0; ii<4; ii++) {
            const int i = (tyA<<2) + ii;
            a4[ii] = (s <= i) ? accA[ii][ss]*expf(Lc[i]-Lc[s]) : 0.f;
        }
        *(float4*)&At[s*68 + (tyA<<2)] = av;
        *(float4*)&g_At[((size_t)bhch*CHK + s)*CHK + (tyA<<2)] = av;
    }
    __syncthreads();
    if (tid < CHK) {
        float s = 0.f;
        for (int sI = 0; sI < CHK; sI++) s += At[sI*68 + tid];
        g_rsum[(size_t)bhch*CHK + tid] = s;
    }
}

// =====================================================================
// state_kernel: sequential S/z propagation only.
// =====================================================================
#define STATE_SMEM ((128*68 + 64*36 + 128*36 + 128 + 64 + 4) * 4)

__global__ __launch_bounds__(256) void state_kernel(
    const float* __restrict__ gk, const float* __restrict__ gv)
{
    extern __shared__ float sm[];
    float* Kt  = sm;                 // [128][68]
    float* Vs  = Kt  + 128*68;       // [64][36]
    float* Ssm = Vs  + 64*36;        // [128][36]
    float* z   = Ssm + 128*36;       // [128]
    float* ksc = z   + 128;          // [64]
    float* Gs  = ksc + 64;           // [1]

    const int tid   = threadIdx.x;
    const int bh    = blockIdx.x / NSPLIT;
    const int split = blockIdx.x % NSPLIT;

    const float* kp = gk + (size_t)bh*LL*DD;
    const float* vp = gv + (size_t)bh*LL*DD + split*DV;

    const int txO = tid & 7, tyO = tid >> 3;

    for (int i = tid; i < 128*36; i += 256) Ssm[i] = 0.f;
    if (tid < 128) z[tid] = 0.f;

    for (int ch = 0; ch < NCH; ch++) {
        const int t0 = ch * CHK;
        const int bhch = bh * NCH + ch;
        __syncthreads();
        for (int idx = tid; idx < CHK*128; idx += 256) {
            const int i = idx >> 7, d = idx & 127;
            Kt[d*68 + i] = kp[(size_t)(t0+i)*DD + d];
        }
        for (int idx = tid; idx < CHK*DV; idx += 256) {
            const int i = idx >> 5, e = idx & 31;
            Vs[i*36 + e] = vp[(size_t)(t0+i)*DD + e];
        }
        if (tid < CHK) ksc[tid] = g_ksc[(size_t)bhch*CHK + tid];
        if (tid == 0) Gs[0] = g_eLc[(size_t)bhch*CHK + CHK-1];
        __syncthreads();

        for (int f = tid; f < 128*8; f += 256) {
            const int d = f >> 3, eg = f & 7;
            *(float4*)&g_Sst[((size_t)bhch*DD + d)*DD + split*DV + eg*4] =
                *(float4*)&Ssm[d*36 + eg*4];
        }
        if (split == 0 && tid < 128)
            g_zst[(size_t)bhch*DD + tid] = z[tid];
        __syncthreads();

        const float G = Gs[0];
        {
            float accS[4][4];
            #pragma unroll
            for (int i=0;i<4;i++){accS[i][0]=0;accS[i][1]=0;accS[i][2]=0;accS[i][3]=0;}
            const int d0 = tyO << 2;
            for (int s = 0; s < CHK; s++) {
                const float sc = ksc[s];
                const float4 v4 = *(float4*)&Vs[s*36 + (txO<<2)];
                float kk[4];
                #pragma unroll
                for (int dd=0; dd<4; dd++) kk[dd] = Kt[(d0+dd)*68 + s] * sc;
                #pragma unroll
                for (int dd=0; dd<4; dd++) {
                    accS[dd][0]=fmaf(kk[dd],v4.x,accS[dd][0]);
                    accS[dd][1]=fmaf(kk[dd],v4.y,accS[dd][1]);
                    accS[dd][2]=fmaf(kk[dd],v4.z,accS[dd][2]);
                    accS[dd][3]=fmaf(kk[dd],v4.w,accS[dd][3]);
                }
            }
            #pragma unroll
            for (int dd=0; dd<4; dd++) {
                float4 sv = *(float4*)&Ssm[(d0+dd)*36 + (txO<<2)];
                sv.x = fmaf(G, sv.x, accS[dd][0]);
                sv.y = fmaf(G, sv.y, accS[dd][1]);
                sv.z = fmaf(G, sv.z, accS[dd][2]);
                sv.w = fmaf(G, sv.w, accS[dd][3]);
                *(float4*)&Ssm[(d0+dd)*36 + (txO<<2)] = sv;
            }
        }
        if (tid < 128) {
            float zv = z[tid] * G;
            for (int s = 0; s < CHK; s++) zv = fmaf(Kt[tid*68 + s], ksc[s], zv);
            z[tid] = zv;
        }
    }
}

// =====================================================================
// y_kernel: per (bh, chunk), fully parallel output.
// =====================================================================
#define Y_SMEM ((128*68 + 64*68 + 64*132 + 128*132 + 128 + 3*64) * 4)

__global__ __launch_bounds__(256) void y_kernel(
    const float* __restrict__ gq, const float* __restrict__ gv,
    __nv_bfloat16* __restrict__ yhi, __nv_bfloat16* __restrict__ ylo)
{
    extern __shared__ float sm[];
    float* Qt  = sm;                 // [128][68]
    float* At  = Qt  + 128*68;       // [64][68] s-major
    float* Vs  = At  + 64*68;        // [64][132]
    float* Ss  = Vs  + 64*132;       // [128][132]
    float* z   = Ss  + 128*132;      // [128]
    float* rsum= z   + 128;          // [64]
    float* eLc = rsum+ 64;           // [64]
    float* qz  = eLc + 64;           // [64]

    const int tid  = threadIdx.x;
    const int bhch = blockIdx.x;
    const int bh   = bhch >> 5, ch = bhch & 31;
    const int b    = bh >> 4, hd = bh & 15;
    const int t0   = ch * CHK;

    const float* qp = gq + (size_t)bh*LL*DD;
    const float* vp = gv + (size_t)bh*LL*DD;

    for (int idx = tid; idx < CHK*128; idx += 256) {
        const int i = idx >> 7, d = idx & 127;
        Qt[d*68 + i] = qp[(size_t)(t0+i)*DD + d];
    }
    for (int f = tid; f < 64*16; f += 256) {
        const int s = f >> 4, i0 = (f & 15) << 2;
        *(float4*)&At[s*68 + i0] =
            *(const float4*)&g_At[((size_t)bhch*CHK + s)*CHK + i0];
    }
    for (int f = tid; f < 64*32; f += 256) {
        const int s = f >> 5, e4 = (f & 31) << 2;
        *(float4*)&Vs[s*132 + e4] = *(const float4*)&vp[(size_t)(t0+s)*DD + e4];
    }
    for (int f = tid; f < 128*32; f += 256) {
        const int d = f >> 5, e4 = (f & 31) << 2;
        *(float4*)&Ss[d*132 + e4] =
            *(const float4*)&g_Sst[((size_t)bhch*DD + d)*DD + e4];
    }
    if (tid < 128) z[tid] = g_zst[(size_t)bhch*DD + tid];
    if (tid < 64) {
        rsum[tid] = g_rsum[(size_t)bhch*CHK + tid];
        eLc[tid]  = g_eLc [(size_t)bhch*CHK + tid];
    }
    __syncthreads();

    if (tid < CHK) {
        float s = 0.f;
        for (int d = 0; d < 128; d++) s = fmaf(Qt[d*68 + tid], z[d], s);
        qz[tid] = s;
    }

    const int txO = tid & 31, tyO = tid >> 5;      // 8 i-rows x 4 e-cols each
    float oA[8][4], oI[8][4];
    #pragma unroll
    for (int r=0;r<8;r++)
        #pragma unroll
        for (int c=0;c<4;c++) { oA[r][c]=0.f; oI[r][c]=0.f; }

    for (int s = 0; s < CHK; s++) {
        const float4 v4 = *(float4*)&Vs[s*132 + (txO<<2)];
        #pragma unroll
        for (int r = 0; r < 8; r++) {
            const float a = At[s*68 + (tyO<<3) + r];
            oA[r][0]=fmaf(a,v4.x,oA[r][0]); oA[r][1]=fmaf(a,v4.y,oA[r][1]);
            oA[r][2]=fmaf(a,v4.z,oA[r][2]); oA[r][3]=fmaf(a,v4.w,oA[r][3]);
        }
    }
    for (int d = 0; d < 128; d++) {
        const float4 s4 = *(float4*)&Ss[d*132 + (txO<<2)];
        #pragma unroll
        for (int r = 0; r < 8; r++) {
            const float q = Qt[d*68 + (tyO<<3) + r];
            oI[r][0]=fmaf(q,s4.x,oI[r][0]); oI[r][1]=fmaf(q,s4.y,oI[r][1]);
            oI[r][2]=fmaf(q,s4.z,oI[r][2]); oI[r][3]=fmaf(q,s4.w,oI[r][3]);
        }
    }
    __syncthreads();

    #pragma unroll
    for (int r = 0; r < 8; r++) {
        const int i = (tyO<<3) + r;
        const float g = eLc[i];
        const float inv = 1.f / (rsum[i] + g*qz[i] + 1e-6f);
        float o[4];
        #pragma unroll
        for (int c = 0; c < 4; c++) o[c] = (oA[r][c] + g*oI[r][c]) * inv;
        __nv_bfloat16 hb[4], lb[4];
        #pragma unroll
        for (int u = 0; u < 4; u++) {
            hb[u] = __float2bfloat16(o[u]);
            lb[u] = __float2bfloat16(o[u] - __bfloat162float(hb[u]));
        }
        const size_t off = ((size_t)(b*LL + t0 + i))*HID + hd*DD + (txO<<2);
        __nv_bfloat162 ph0; ph0.x = hb[0]; ph0.y = hb[1];
        __nv_bfloat162 ph1; ph1.x = hb[2]; ph1.y = hb[3];
        __nv_bfloat162 pl0; pl0.x = lb[0]; pl0.y = lb[1];
        __nv_bfloat162 pl1; pl1.x = lb[2]; pl1.y = lb[3];
        *(__nv_bfloat162*)(yhi + off)     = ph0;
        *(__nv_bfloat162*)(yhi + off + 2) = ph1;
        *(__nv_bfloat162*)(ylo + off)     = pl0;
        *(__nv_bfloat162*)(ylo + off + 2) = pl1;
    }
}

// =====================================================================
// launch
// =====================================================================
extern "C" void kernel_launch(void* const* d_in, const int* in_sizes, int n_in,
                              void* d_out, int out_size)
{
    const float* x  = (const float*)d_in[0];
    const float* Wq = (const float*)d_in[1];
    const float* Wk = (const float*)d_in[2];
    const float* Wv = (const float*)d_in[3];
    const float* Wg = (const float*)d_in[4];
    const float* bg = (const float*)d_in[5];
    const float* Wo = (const float*)d_in[6];
    const float* bo = (const float*)d_in[7];
    float* out = (float*)d_out;

    float *q, *k, *v, *beta;
    __nv_bfloat16 *ahi, *alo, *whi, *wlo;
    cudaGetSymbolAddress((void**)&q,    g_q);
    cudaGetSymbolAddress((void**)&k,    g_k);
    cudaGetSymbolAddress((void**)&v,    g_v);
    cudaGetSymbolAddress((void**)&beta, g_beta);
    cudaGetSymbolAddress((void**)&ahi,  g_ahi);
    cudaGetSymbolAddress((void**)&alo,  g_alo);
    cudaGetSymbolAddress((void**)&whi,  g_whi);
    cudaGetSymbolAddress((void**)&wlo,  g_wlo);

    cudaFuncSetAttribute(gemm_tc_kernel,
        cudaFuncAttributeMaxDynamicSharedMemorySize, GEMM_SMEM);
    cudaFuncSetAttribute(chunk_kernel,
        cudaFuncAttributeMaxDynamicSharedMemorySize, CHUNK_SMEM);
    cudaFuncSetAttribute(state_kernel,
        cudaFuncAttributeMaxDynamicSharedMemorySize, STATE_SMEM);
    cudaFuncSetAttribute(y_kernel,
        cudaFuncAttributeMaxDynamicSharedMemorySize, Y_SMEM);

    const size_t WSZ = (size_t)HID*HID;

    // launch order: fused QKV GEMM sits at index 4 (the ncu capture slot)
    rope_table_kernel<<<(LL*64 + 255)/256, 256>>>();                       // 0
    cvt_w_kernel<<<dim3(HID/32, HID/32, 4), dim3(32, 8)>>>(                // 1
        Wq, Wk, Wv, Wo, whi, wlo);
    cvt_split_kernel<<<(MM*HID/4 + 255)/256, 256>>>(                       // 2
        (const float4*)x, ahi, alo, MM*HID/4);
    beta_kernel<<<MM, 512>>>(x, Wg, bg, beta);                             // 3

    gemm_tc_kernel<<<dim3(48, MM/128), 256, GEMM_SMEM>>>(                  // 4
        ahi, alo, whi, wlo, nullptr, nullptr, q, k, v, 1, MM, 3*HID, HID);

    chunk_kernel<<<NBH*NCH, 256, CHUNK_SMEM>>>(q, k, beta);                // 5
    state_kernel<<<NBH*NSPLIT, 256, STATE_SMEM>>>(k, v);                   // 6
    y_kernel<<<NBH*NCH, 256, Y_SMEM>>>(q, v, ahi, alo);                    // 7

    gemm_tc_kernel<<<dim3(HID/128, MM/128), 256, GEMM_SMEM>>>(             // 8
        ahi, alo, whi + 3*WSZ, wlo + 3*WSZ, bo, out,
        nullptr, nullptr, nullptr, 0, MM, HID, HID);
}

// round 13
// speedup vs baseline: 1.0574x; 1.0574x over previous
#include <cuda_runtime.h>
#include <cuda_bf16.h>
#include <math.h>
#include <stdint.h>

// Problem constants
#define BB   2
#define LL   2048
#define HID  2048
#define HH   16
#define DD   128
#define MM   (BB*LL)          // 4096
#define CHK  64               // scan chunk length
#define NCH  (LL/CHK)         // 32 chunks
#define DV   32               // v-dim split per state block
#define NSPLIT 4              // 128 / DV
#define NBH  (BB*HH)          // 32

// ---------------- device scratch (no cudaMalloc allowed) ----------------
__device__ __align__(256) float g_q   [MM*HID];     // phi_q [b*H+h][t][d]
__device__ __align__(256) float g_k   [MM*HID];     // phi_k
__device__ __align__(256) float g_v   [MM*HID];     // v
__device__ __align__(256) float g_beta[NBH*LL];     // [b*H+h][t]
__device__ __align__(256) float g_wgt [HH*HID];     // Wg^T [h][d]

// chunk-factored scan scratch
__device__ __align__(256) float g_At  [NBH*NCH*CHK*CHK];  // decayed+masked A, [bhch][s][i]
__device__ __align__(256) float g_rsum[NBH*NCH*CHK];
__device__ __align__(256) float g_eLc [NBH*NCH*CHK];
__device__ __align__(256) float g_ksc [NBH*NCH*CHK];
__device__ __align__(256) float g_Sst [NBH*NCH*DD*DD];    // S_prev per chunk
__device__ __align__(256) float g_zst [NBH*NCH*DD];       // z_prev per chunk

// bf16 split buffers
__device__ __align__(256) __nv_bfloat16 g_ahi[MM*HID];       // x (then y) hi
__device__ __align__(256) __nv_bfloat16 g_alo[MM*HID];       // x (then y) lo
__device__ __align__(256) __nv_bfloat16 g_whi[4*HID*HID];    // W^T hi (q,k,v,o concat)
__device__ __align__(256) __nv_bfloat16 g_wlo[4*HID*HID];    // W^T lo

// rope tables
__device__ float g_cos[LL*64];
__device__ float g_sin[LL*64];

// =====================================================================
// sm_80-era primitives (legal on plain sm_103 ptxas target)
// =====================================================================
__device__ __forceinline__ uint32_t smem_u32(const void* p) {
    uint32_t a;
    asm("{ .reg .u64 t; cvta.to.shared.u64 t, %1; cvt.u32.u64 %0, t; }"
        : "=r"(a) : "l"(p));
    return a;
}
__device__ __forceinline__ void ldsm_x4(uint32_t addr, uint32_t& r0, uint32_t& r1,
                                        uint32_t& r2, uint32_t& r3) {
    asm volatile("ldmatrix.sync.aligned.m8n8.x4.shared.b16 {%0,%1,%2,%3}, [%4];"
        : "=r"(r0), "=r"(r1), "=r"(r2), "=r"(r3) : "r"(addr));
}
__device__ __forceinline__ void mma_bf16(float* c, const uint32_t* a, const uint32_t* b) {
    asm volatile(
        "mma.sync.aligned.m16n8k16.row.col.f32.bf16.bf16.f32 "
        "{%0,%1,%2,%3}, {%4,%5,%6,%7}, {%8,%9}, {%0,%1,%2,%3};"
        : "+f"(c[0]), "+f"(c[1]), "+f"(c[2]), "+f"(c[3])
        : "r"(a[0]), "r"(a[1]), "r"(a[2]), "r"(a[3]), "r"(b[0]), "r"(b[1]));
}
#define CP_ASYNC16(dst, src) \
    asm volatile("cp.async.cg.shared.global [%0], [%1], 16;" :: "r"(dst), "l"(src))
#define CP_COMMIT() asm volatile("cp.async.commit_group;" ::: "memory")
#define CP_WAIT(n)  asm volatile("cp.async.wait_group %0;" :: "n"(n) : "memory")

// =====================================================================
// bf16 split conversion: hi = bf16(x), lo = bf16(x - hi)
// =====================================================================
__global__ __launch_bounds__(256) void cvt_split_kernel(
    const float4* __restrict__ in, __nv_bfloat16* __restrict__ hi,
    __nv_bfloat16* __restrict__ lo, int n4)
{
    int i = blockIdx.x * 256 + threadIdx.x;
    if (i >= n4) return;
    float4 v = in[i];
    float a[4] = {v.x, v.y, v.z, v.w};
    __nv_bfloat16 hb[4], lb[4];
    #pragma unroll
    for (int j = 0; j < 4; j++) {
        hb[j] = __float2bfloat16(a[j]);
        lb[j] = __float2bfloat16(a[j] - __bfloat162float(hb[j]));
    }
    __nv_bfloat162 h0, h1, l0, l1;
    h0.x = hb[0]; h0.y = hb[1]; h1.x = hb[2]; h1.y = hb[3];
    l0.x = lb[0]; l0.y = lb[1]; l1.x = lb[2]; l1.y = lb[3];
    *(__nv_bfloat162*)(hi + 4*(size_t)i)     = h0;
    *(__nv_bfloat162*)(hi + 4*(size_t)i + 2) = h1;
    *(__nv_bfloat162*)(lo + 4*(size_t)i)     = l0;
    *(__nv_bfloat162*)(lo + 4*(size_t)i + 2) = l1;
}

// All 4 weights in one launch: W [K=HID][N=HID] fp32 -> W^T hi/lo bf16 [N][K]
__global__ __launch_bounds__(256) void cvt_w_kernel(
    const float* __restrict__ W0, const float* __restrict__ W1,
    const float* __restrict__ W2, const float* __restrict__ W3,
    __nv_bfloat16* __restrict__ th, __nv_bfloat16* __restrict__ tl)
{
    __shared__ float t[32][33];
    const float* W = (blockIdx.z == 0) ? W0 : (blockIdx.z == 1) ? W1
                   : (blockIdx.z == 2) ? W2 : W3;
    const size_t obase = (size_t)blockIdx.z * HID * HID;
    const int k0 = blockIdx.y * 32, n0 = blockIdx.x * 32;
    const int tx = threadIdx.x, ty = threadIdx.y;   // block (32,8)
    for (int i = ty; i < 32; i += 8)
        t[i][tx] = W[(size_t)(k0 + i) * HID + n0 + tx];
    __syncthreads();
    for (int i = ty; i < 32; i += 8) {
        float x = t[tx][i];                    // W[k0+tx][n0+i]
        __nv_bfloat16 h = __float2bfloat16(x);
        __nv_bfloat16 l = __float2bfloat16(x - __bfloat162float(h));
        size_t o = obase + (size_t)(n0 + i) * HID + k0 + tx;
        th[o] = h; tl[o] = l;
    }
}

// =====================================================================
// mma.sync GEMM with fused epilogue (R10 mainloop — the fastest verified).
// =====================================================================
#define GEMM_SMEM (3 * 4 * 16384)   // 3 stages x (Ah,Al,Bh,Bl) x 16KB = 192KB

__global__ __launch_bounds__(256, 1) void gemm_tc_kernel(
    const __nv_bfloat16* __restrict__ Ah, const __nv_bfloat16* __restrict__ Al,
    const __nv_bfloat16* __restrict__ Bh, const __nv_bfloat16* __restrict__ Bl,
    const float* __restrict__ bias, float* __restrict__ C,
    float* __restrict__ outQ, float* __restrict__ outK, float* __restrict__ outV,
    int fuse, int M, int N, int K)
{
    extern __shared__ __align__(1024) char smem[];
    const uint32_t sbase = smem_u32(smem);

    const int tid  = threadIdx.x;
    const int wid  = tid >> 5, lane = tid & 31;
    const int wm   = wid >> 2, wn = wid & 3;       // warp grid 2x4
    const int m0   = blockIdx.y * 128;
    const int bn0  = blockIdx.x * 128;             // row into B (concat N)

    const __nv_bfloat16* gsrc[4] = {Ah, Al, Bh, Bl};
    const int NS = K >> 6;                          // K/64 stages

    auto load_stage = [&](int buf, int k0e) {
        const uint32_t bs = sbase + buf * 65536;
        #pragma unroll
        for (int p = 0; p < 16; p++) {
            int idx = tid + p * 256;
            int j   = idx >> 10;
            int i   = idx & 1023;
            int r   = i >> 3, ch = i & 7;
            int phys = ch ^ (r & 7);
            uint32_t dst = bs + j * 16384 + r * 128 + phys * 16;
            int grow = (j < 2 ? m0 : bn0) + r;
            const __nv_bfloat16* src = gsrc[j] + (size_t)grow * K + k0e + ch * 8;
            CP_ASYNC16(dst, src);
        }
        CP_COMMIT();
    };

    const int lw  = lane & 7;
    const int gA  = (lane >> 4) & 1;
    const int gB  = (lane >> 3) & 1;
    uint32_t offA[4], offB[2];
    #pragma unroll
    for (int mi = 0; mi < 4; mi++)
        offA[mi] = (uint32_t)(wm * 64 + mi * 16 + (lane & 15)) * 128;
    #pragma unroll
    for (int p = 0; p < 2; p++)
        offB[p] = (uint32_t)(wn * 32 + p * 16 + ((lane >> 4) & 1) * 8 + lw) * 128;

    float acc[4][4][4];
    #pragma unroll
    for (int mi = 0; mi < 4; mi++)
        #pragma unroll
        for (int ni = 0; ni < 4; ni++) {
            acc[mi][ni][0] = 0.f; acc[mi][ni][1] = 0.f;
            acc[mi][ni][2] = 0.f; acc[mi][ni][3] = 0.f;
        }

    load_stage(0, 0);
    load_stage(1, 64);

    for (int s = 0; s < NS; s++) {
        if (s + 1 < NS) { CP_WAIT(1); } else { CP_WAIT(0); }
        __syncthreads();
        if (s + 2 < NS) load_stage((s + 2) % 3, (s + 2) * 64);

        const uint32_t stage = sbase + (s % 3) * 65536;
        #pragma unroll
        for (int kk = 0; kk < 4; kk++) {
            const uint32_t swA = (uint32_t)(((kk * 2 + gA) ^ lw) << 4);
            const uint32_t swB = (uint32_t)(((kk * 2 + gB) ^ lw) << 4);
            uint32_t ah[4][4], al[4][4];
            #pragma unroll
            for (int mi = 0; mi < 4; mi++) {
                uint32_t aA = stage + offA[mi] + swA;
                ldsm_x4(aA,          ah[mi][0], ah[mi][1], ah[mi][2], ah[mi][3]);
                ldsm_x4(aA + 16384,  al[mi][0], al[mi][1], al[mi][2], al[mi][3]);
            }
            uint32_t bh[4][2], bl[4][2];
            #pragma unroll
            for (int p = 0; p < 2; p++) {
                uint32_t aB = stage + 32768 + offB[p] + swB;
                uint32_t r0, r1, r2, r3;
                ldsm_x4(aB, r0, r1, r2, r3);
                bh[2*p][0] = r0; bh[2*p][1] = r1; bh[2*p+1][0] = r2; bh[2*p+1][1] = r3;
                ldsm_x4(aB + 16384, r0, r1, r2, r3);
                bl[2*p][0] = r0; bl[2*p][1] = r1; bl[2*p+1][0] = r2; bl[2*p+1][1] = r3;
            }
            #pragma unroll
            for (int mi = 0; mi < 4; mi++)
                #pragma unroll
                for (int ni = 0; ni < 4; ni++) {
                    mma_bf16(acc[mi][ni], ah[mi], bh[ni]);
                    mma_bf16(acc[mi][ni], ah[mi], bl[ni]);
                    mma_bf16(acc[mi][ni], al[mi], bh[ni]);
                }
        }
        __syncthreads();
    }

    const int qr = lane >> 2, qc = (lane & 3) * 2;

    if (!fuse) {
        #pragma unroll
        for (int mi = 0; mi < 4; mi++) {
            const int row = m0 + wm * 64 + mi * 16 + qr;
            #pragma unroll
            for (int ni = 0; ni < 4; ni++) {
                const int col = bn0 + wn * 32 + ni * 8 + qc;
                float b0 = bias ? bias[col]     : 0.f;
                float b1 = bias ? bias[col + 1] : 0.f;
                float2 v0 = make_float2(acc[mi][ni][0] + b0, acc[mi][ni][1] + b1);
                float2 v1 = make_float2(acc[mi][ni][2] + b0, acc[mi][ni][3] + b1);
                *(float2*)(C + (size_t)row * N + col)       = v0;
                *(float2*)(C + (size_t)(row + 8) * N + col) = v1;
            }
        }
        return;
    }

    // fused QKV epilogue
    float* st = (float*)smem;                      // [128][132]
    #pragma unroll
    for (int mi = 0; mi < 4; mi++) {
        const int r0r = wm * 64 + mi * 16 + qr;
        #pragma unroll
        for (int ni = 0; ni < 4; ni++) {
            const int c = wn * 32 + ni * 8 + qc;
            *(float2*)&st[(size_t)r0r * 132 + c] =
                make_float2(acc[mi][ni][0], acc[mi][ni][1]);
            *(float2*)&st[(size_t)(r0r + 8) * 132 + c] =
                make_float2(acc[mi][ni][2], acc[mi][ni][3]);
        }
    }
    __syncthreads();

    const int hIdx = blockIdx.x & 15;
    if (blockIdx.x < 32) {
        float* dstBase = (blockIdx.x < 16) ? outQ : outK;
        const int j = tid & 63;
        #pragma unroll 4
        for (int it = 0; it < 32; it++) {
            const int r = (tid >> 6) + it * 4;
            const int tg = m0 + r;
            const int bI = tg >> 11, t = tg & (LL - 1);
            float xe = st[(size_t)r * 132 + j];
            float xo = st[(size_t)r * 132 + 64 + j];
            float c = g_cos[t * 64 + j];
            float s = g_sin[t * 64 + j];
            float oe = xe * c - xo * s;
            float oo = xe * s + xo * c;
            oe = (oe > 0.f) ? (oe + 1.f) : expf(oe);
            oo = (oo > 0.f) ? (oo + 1.f) : expf(oo);
            float* dst = dstBase + ((size_t)(bI * HH + hIdx) * LL + t) * DD;
            dst[j]      = oe;
            dst[j + 64] = oo;
        }
    } else {
        const int d = tid & 127;
        #pragma unroll 4
        for (int it = 0; it < 64; it++) {
            const int r = (tid >> 7) + it * 2;
            const int tg = m0 + r;
            const int bI = tg >> 11, t = tg & (LL - 1);
            outV[((size_t)(bI * HH + hIdx) * LL + t) * DD + d] =
                st[(size_t)r * 132 + d];
        }
    }
}

// =====================================================================
// rope table + Wg transpose (one launch)
// =====================================================================
__global__ __launch_bounds__(256) void rope_table_kernel(const float* __restrict__ Wg)
{
    int idx = blockIdx.x * 256 + threadIdx.x;
    if (idx < LL * 64) {
        int t = idx >> 6, j = idx & 63;
        float invf = (float)exp(-(double)j * 9.210340371976184 / 64.0);
        float ang = (float)t * invf;
        double sd, cd; sincos((double)ang, &sd, &cd);
        g_cos[idx] = (float)cd;
        g_sin[idx] = (float)sd;
    }
    int widx = idx - LL * 64;
    if (widx >= 0 && widx < HH * HID) {
        int w = widx >> 11, d = widx & (HID - 1);
        g_wgt[widx] = Wg[d * HH + w];    // WgT[w][d]
    }
}

// =====================================================================
// beta = clip(sigmoid(x @ Wg + bg), 0.8, 0.9995), stored [b*H+h][t].
// Coalesced rewrite: one block per 16 token-rows, one warp per head.
// Warp holds its WgT row in 64 registers; x rows read coalesced.
// =====================================================================
__global__ __launch_bounds__(512) void beta_kernel(
    const float* __restrict__ x, const float* __restrict__ bg,
    float* __restrict__ beta)
{
    const int w = threadIdx.x >> 5, lane = threadIdx.x & 31;   // warp = head
    const int m0 = blockIdx.x * 16;

    float wreg[64];
    const float* wgt = g_wgt + (size_t)w * HID + lane;
    #pragma unroll
    for (int i = 0; i < 64; i++) wreg[i] = wgt[i * 32];

    const float bgw = bg[w];
    for (int r = 0; r < 16; r++) {
        const int m = m0 + r;
        const float* xr = x + (size_t)m * HID + lane;
        float s = 0.f;
        #pragma unroll
        for (int i = 0; i < 64; i++) s = fmaf(wreg[i], xr[i * 32], s);
        #pragma unroll
        for (int o = 16; o; o >>= 1) s += __shfl_xor_sync(0xffffffffu, s, o);
        if (lane == 0) {
            s += bgw;
            float bt = 1.f / (1.f + expf(-s));
            bt = fminf(fmaxf(bt, 0.8f), 0.9995f);
            const int b = m >> 11, t = m & (LL - 1);
            beta[(size_t)(b * HH + w) * LL + t] = bt;
        }
    }
}

// =====================================================================
// chunk_kernel: per (bh, chunk), fully parallel.
// =====================================================================
#define CHUNK_SMEM ((128*68*2 + 64*68 + 2*64) * 4)

__global__ __launch_bounds__(256) void chunk_kernel(
    const float* __restrict__ gq, const float* __restrict__ gk,
    const float* __restrict__ gbeta)
{
    extern __shared__ float sm[];
    float* Qt = sm;                  // [128][68]
    float* Kt = Qt + 128*68;
    float* At = Kt + 128*68;         // [64][68] s-major
    float* bl = At + 64*68;          // [64]
    float* Lc = bl + 64;             // [64]

    const int tid  = threadIdx.x;
    const int bhch = blockIdx.x;
    const int bh   = bhch >> 5, ch = bhch & 31;
    const int t0   = ch * CHK;

    const float* qp = gq + (size_t)bh*LL*DD;
    const float* kp = gk + (size_t)bh*LL*DD;
    const float* bp = gbeta + (size_t)bh*LL;

    for (int idx = tid; idx < CHK*128; idx += 256) {
        const int i = idx >> 7, d = idx & 127;
        Qt[d*68 + i] = qp[(size_t)(t0+i)*DD + d];
        Kt[d*68 + i] = kp[(size_t)(t0+i)*DD + d];
    }
    if (tid < CHK) bl[tid] = logf(bp[t0+tid]);
    __syncthreads();
    if (tid == 0) {
        float a = 0.f;
        for (int i = 0; i < CHK; i++) { a += bl[i]; Lc[i] = a; }
    }
    __syncthreads();

    const int txA = tid & 15, tyA = tid >> 4;
    float accA[4][4];
    #pragma unroll
    for (int i=0;i<4;i++) { accA[i][0]=0;accA[i][1]=0;accA[i][2]=0;accA[i][3]=0; }
    for (int k = 0; k < 128; k++) {
        float4 qa = *(float4*)&Qt[k*68 + (tyA<<2)];
        float4 kb = *(float4*)&Kt[k*68 + (txA<<2)];
        const float qv[4] = {qa.x,qa.y,qa.z,qa.w};
        const float kv[4] = {kb.x,kb.y,kb.z,kb.w};
        #pragma unroll
        for (int i=0;i<4;i++)
            #pragma unroll
            for (int s=0;s<4;s++)
                accA[i][s] = fmaf(qv[i], kv[s], accA[i][s]);
    }
    if (tid < CHK) {
        g_eLc[(size_t)bhch*CHK + tid] = expf(Lc[tid]);
        g_ksc[(size_t)bhch*CHK + tid] = expf(Lc[CHK-1] - Lc[tid]);
    }
    #pragma unroll
    for (int ss=0; ss<4; ss++) {
        const int s = (txA<<2) + ss;
        float4 av;
        float* a4 = (float*)&av;
        #pragma unroll
        for (int ii=0; ii<4; ii++) {
            const int i = (tyA<<2) + ii;
            a4[ii] = (s <= i) ? accA[ii][ss]*expf(Lc[i]-Lc[s]) : 0.f;
        }
        *(float4*)&At[s*68 + (tyA<<2)] = av;
        *(float4*)&g_At[((size_t)bhch*CHK + s)*CHK + (tyA<<2)] = av;
    }
    __syncthreads();
    if (tid < CHK) {
        float s = 0.f;
        for (int sI = 0; sI < CHK; sI++) s += At[sI*68 + tid];
        g_rsum[(size_t)bhch*CHK + tid] = s;
    }
}

// =====================================================================
// state_kernel: sequential S/z propagation only.
// =====================================================================
#define STATE_SMEM ((128*68 + 64*36 + 128*36 + 128 + 64 + 4) * 4)

__global__ __launch_bounds__(256) void state_kernel(
    const float* __restrict__ gk, const float* __restrict__ gv)
{
    extern __shared__ float sm[];
    float* Kt  = sm;                 // [128][68]
    float* Vs  = Kt  + 128*68;       // [64][36]
    float* Ssm = Vs  + 64*36;        // [128][36]
    float* z   = Ssm + 128*36;       // [128]
    float* ksc = z   + 128;          // [64]
    float* Gs  = ksc + 64;           // [1]

    const int tid   = threadIdx.x;
    const int bh    = blockIdx.x / NSPLIT;
    const int split = blockIdx.x % NSPLIT;

    const float* kp = gk + (size_t)bh*LL*DD;
    const float* vp = gv + (size_t)bh*LL*DD + split*DV;

    const int txO = tid & 7, tyO = tid >> 3;

    for (int i = tid; i < 128*36; i += 256) Ssm[i] = 0.f;
    if (tid < 128) z[tid] = 0.f;

    for (int ch = 0; ch < NCH; ch++) {
        const int t0 = ch * CHK;
        const int bhch = bh * NCH + ch;
        __syncthreads();
        for (int idx = tid; idx < CHK*128; idx += 256) {
            const int i = idx >> 7, d = idx & 127;
            Kt[d*68 + i] = kp[(size_t)(t0+i)*DD + d];
        }
        for (int idx = tid; idx < CHK*DV; idx += 256) {
            const int i = idx >> 5, e = idx & 31;
            Vs[i*36 + e] = vp[(size_t)(t0+i)*DD + e];
        }
        if (tid < CHK) ksc[tid] = g_ksc[(size_t)bhch*CHK + tid];
        if (tid == 0) Gs[0] = g_eLc[(size_t)bhch*CHK + CHK-1];
        __syncthreads();

        for (int f = tid; f < 128*8; f += 256) {
            const int d = f >> 3, eg = f & 7;
            *(float4*)&g_Sst[((size_t)bhch*DD + d)*DD + split*DV + eg*4] =
                *(float4*)&Ssm[d*36 + eg*4];
        }
        if (split == 0 && tid < 128)
            g_zst[(size_t)bhch*DD + tid] = z[tid];
        __syncthreads();

        const float G = Gs[0];
        {
            float accS[4][4];
            #pragma unroll
            for (int i=0;i<4;i++){accS[i][0]=0;accS[i][1]=0;accS[i][2]=0;accS[i][3]=0;}
            const int d0 = tyO << 2;
            for (int s = 0; s < CHK; s++) {
                const float sc = ksc[s];
                const float4 v4 = *(float4*)&Vs[s*36 + (txO<<2)];
                float kk[4];
                #pragma unroll
                for (int dd=0; dd<4; dd++) kk[dd] = Kt[(d0+dd)*68 + s] * sc;
                #pragma unroll
                for (int dd=0; dd<4; dd++) {
                    accS[dd][0]=fmaf(kk[dd],v4.x,accS[dd][0]);
                    accS[dd][1]=fmaf(kk[dd],v4.y,accS[dd][1]);
                    accS[dd][2]=fmaf(kk[dd],v4.z,accS[dd][2]);
                    accS[dd][3]=fmaf(kk[dd],v4.w,accS[dd][3]);
                }
            }
            #pragma unroll
            for (int dd=0; dd<4; dd++) {
                float4 sv = *(float4*)&Ssm[(d0+dd)*36 + (txO<<2)];
                sv.x = fmaf(G, sv.x, accS[dd][0]);
                sv.y = fmaf(G, sv.y, accS[dd][1]);
                sv.z = fmaf(G, sv.z, accS[dd][2]);
                sv.w = fmaf(G, sv.w, accS[dd][3]);
                *(float4*)&Ssm[(d0+dd)*36 + (txO<<2)] = sv;
            }
        }
        if (tid < 128) {
            float zv = z[tid] * G;
            for (int s = 0; s < CHK; s++) zv = fmaf(Kt[tid*68 + s], ksc[s], zv);
            z[tid] = zv;
        }
    }
}

// =====================================================================
// y_kernel: per (bh, chunk), fully parallel output.
// =====================================================================
#define Y_SMEM ((128*68 + 64*68 + 64*132 + 128*132 + 128 + 3*64) * 4)

__global__ __launch_bounds__(256) void y_kernel(
    const float* __restrict__ gq, const float* __restrict__ gv,
    __nv_bfloat16* __restrict__ yhi, __nv_bfloat16* __restrict__ ylo)
{
    extern __shared__ float sm[];
    float* Qt  = sm;                 // [128][68]
    float* At  = Qt  + 128*68;       // [64][68] s-major
    float* Vs  = At  + 64*68;        // [64][132]
    float* Ss  = Vs  + 64*132;       // [128][132]
    float* z   = Ss  + 128*132;      // [128]
    float* rsum= z   + 128;          // [64]
    float* eLc = rsum+ 64;           // [64]
    float* qz  = eLc + 64;           // [64]

    const int tid  = threadIdx.x;
    const int bhch = blockIdx.x;
    const int bh   = bhch >> 5, ch = bhch & 31;
    const int b    = bh >> 4, hd = bh & 15;
    const int t0   = ch * CHK;

    const float* qp = gq + (size_t)bh*LL*DD;
    const float* vp = gv + (size_t)bh*LL*DD;

    for (int idx = tid; idx < CHK*128; idx += 256) {
        const int i = idx >> 7, d = idx & 127;
        Qt[d*68 + i] = qp[(size_t)(t0+i)*DD + d];
    }
    for (int f = tid; f < 64*16; f += 256) {
        const int s = f >> 4, i0 = (f & 15) << 2;
        *(float4*)&At[s*68 + i0] =
            *(const float4*)&g_At[((size_t)bhch*CHK + s)*CHK + i0];
    }
    for (int f = tid; f < 64*32; f += 256) {
        const int s = f >> 5, e4 = (f & 31) << 2;
        *(float4*)&Vs[s*132 + e4] = *(const float4*)&vp[(size_t)(t0+s)*DD + e4];
    }
    for (int f = tid; f < 128*32; f += 256) {
        const int d = f >> 5, e4 = (f & 31) << 2;
        *(float4*)&Ss[d*132 + e4] =
            *(const float4*)&g_Sst[((size_t)bhch*DD + d)*DD + e4];
    }
    if (tid < 128) z[tid] = g_zst[(size_t)bhch*DD + tid];
    if (tid < 64) {
        rsum[tid] = g_rsum[(size_t)bhch*CHK + tid];
        eLc[tid]  = g_eLc [(size_t)bhch*CHK + tid];
    }
    __syncthreads();

    if (tid < CHK) {
        float s = 0.f;
        for (int d = 0; d < 128; d++) s = fmaf(Qt[d*68 + tid], z[d], s);
        qz[tid] = s;
    }

    const int txO = tid & 31, tyO = tid >> 5;      // 8 i-rows x 4 e-cols each
    float oA[8][4], oI[8][4];
    #pragma unroll
    for (int r=0;r<8;r++)
        #pragma unroll
        for (int c=0;c<4;c++) { oA[r][c]=0.f; oI[r][c]=0.f; }

    for (int s = 0; s < CHK; s++) {
        const float4 v4 = *(float4*)&Vs[s*132 + (txO<<2)];
        #pragma unroll
        for (int r = 0; r < 8; r++) {
            const float a = At[s*68 + (tyO<<3) + r];
            oA[r][0]=fmaf(a,v4.x,oA[r][0]); oA[r][1]=fmaf(a,v4.y,oA[r][1]);
            oA[r][2]=fmaf(a,v4.z,oA[r][2]); oA[r][3]=fmaf(a,v4.w,oA[r][3]);
        }
    }
    for (int d = 0; d < 128; d++) {
        const float4 s4 = *(float4*)&Ss[d*132 + (txO<<2)];
        #pragma unroll
        for (int r = 0; r < 8; r++) {
            const float q = Qt[d*68 + (tyO<<3) + r];
            oI[r][0]=fmaf(q,s4.x,oI[r][0]); oI[r][1]=fmaf(q,s4.y,oI[r][1]);
            oI[r][2]=fmaf(q,s4.z,oI[r][2]); oI[r][3]=fmaf(q,s4.w,oI[r][3]);
        }
    }
    __syncthreads();

    #pragma unroll
    for (int r = 0; r < 8; r++) {
        const int i = (tyO<<3) + r;
        const float g = eLc[i];
        const float inv = 1.f / (rsum[i] + g*qz[i] + 1e-6f);
        float o[4];
        #pragma unroll
        for (int c = 0; c < 4; c++) o[c] = (oA[r][c] + g*oI[r][c]) * inv;
        __nv_bfloat16 hb[4], lb[4];
        #pragma unroll
        for (int u = 0; u < 4; u++) {
            hb[u] = __float2bfloat16(o[u]);
            lb[u] = __float2bfloat16(o[u] - __bfloat162float(hb[u]));
        }
        const size_t off = ((size_t)(b*LL + t0 + i))*HID + hd*DD + (txO<<2);
        __nv_bfloat162 ph0; ph0.x = hb[0]; ph0.y = hb[1];
        __nv_bfloat162 ph1; ph1.x = hb[2]; ph1.y = hb[3];
        __nv_bfloat162 pl0; pl0.x = lb[0]; pl0.y = lb[1];
        __nv_bfloat162 pl1; pl1.x = lb[2]; pl1.y = lb[3];
        *(__nv_bfloat162*)(yhi + off)     = ph0;
        *(__nv_bfloat162*)(yhi + off + 2) = ph1;
        *(__nv_bfloat162*)(ylo + off)     = pl0;
        *(__nv_bfloat162*)(ylo + off + 2) = pl1;
    }
}

// =====================================================================
// launch
// =====================================================================
extern "C" void kernel_launch(void* const* d_in, const int* in_sizes, int n_in,
                              void* d_out, int out_size)
{
    const float* x  = (const float*)d_in[0];
    const float* Wq = (const float*)d_in[1];
    const float* Wk = (const float*)d_in[2];
    const float* Wv = (const float*)d_in[3];
    const float* Wg = (const float*)d_in[4];
    const float* bg = (const float*)d_in[5];
    const float* Wo = (const float*)d_in[6];
    const float* bo = (const float*)d_in[7];
    float* out = (float*)d_out;

    float *q, *k, *v, *beta;
    __nv_bfloat16 *ahi, *alo, *whi, *wlo;
    cudaGetSymbolAddress((void**)&q,    g_q);
    cudaGetSymbolAddress((void**)&k,    g_k);
    cudaGetSymbolAddress((void**)&v,    g_v);
    cudaGetSymbolAddress((void**)&beta, g_beta);
    cudaGetSymbolAddress((void**)&ahi,  g_ahi);
    cudaGetSymbolAddress((void**)&alo,  g_alo);
    cudaGetSymbolAddress((void**)&whi,  g_whi);
    cudaGetSymbolAddress((void**)&wlo,  g_wlo);

    cudaFuncSetAttribute(gemm_tc_kernel,
        cudaFuncAttributeMaxDynamicSharedMemorySize, GEMM_SMEM);
    cudaFuncSetAttribute(chunk_kernel,
        cudaFuncAttributeMaxDynamicSharedMemorySize, CHUNK_SMEM);
    cudaFuncSetAttribute(state_kernel,
        cudaFuncAttributeMaxDynamicSharedMemorySize, STATE_SMEM);
    cudaFuncSetAttribute(y_kernel,
        cudaFuncAttributeMaxDynamicSharedMemorySize, Y_SMEM);

    const size_t WSZ = (size_t)HID*HID;

    // launch order: fused QKV GEMM at index 3 (the slot ncu captured in R12)
    rope_table_kernel<<<(LL*64 + HH*HID + 255)/256, 256>>>(Wg);            // 0
    cvt_w_kernel<<<dim3(HID/32, HID/32, 4), dim3(32, 8)>>>(                // 1
        Wq, Wk, Wv, Wo, whi, wlo);
    cvt_split_kernel<<<(MM*HID/4 + 255)/256, 256>>>(                       // 2
        (const float4*)x, ahi, alo, MM*HID/4);

    gemm_tc_kernel<<<dim3(48, MM/128), 256, GEMM_SMEM>>>(                  // 3
        ahi, alo, whi, wlo, nullptr, nullptr, q, k, v, 1, MM, 3*HID, HID);

    beta_kernel<<<MM/16, 512>>>(x, bg, beta);                              // 4
    chunk_kernel<<<NBH*NCH, 256, CHUNK_SMEM>>>(q, k, beta);                // 5
    state_kernel<<<NBH*NSPLIT, 256, STATE_SMEM>>>(k, v);                   // 6
    y_kernel<<<NBH*NCH, 256, Y_SMEM>>>(q, v, ahi, alo);                    // 7

    gemm_tc_kernel<<<dim3(HID/128, MM/128), 256, GEMM_SMEM>>>(             // 8
        ahi, alo, whi + 3*WSZ, wlo + 3*WSZ, bo, out,
        nullptr, nullptr, nullptr, 0, MM, HID, HID);
}